// round 2
// baseline (speedup 1.0000x reference)
#include <cuda_runtime.h>
#include <cstdint>

// Top-64 per row with ReLU, zeros elsewhere.
// One CTA per row. Row (24576 fp32 = 96 KB) cached in SMEM as monotone uint32
// keys; exact 64th-largest key via MSB-first radix select (11/11/10 bits);
// warp-aggregated histogram atomics; shuffle-based suffix scan; exact tie
// handling matching jax.lax.top_k (lowest index wins among equal values).

constexpr int NCOLS   = 24576;
constexpr int NT      = 512;     // threads per CTA (16 warps)
constexpr int KSEL    = 64;
constexpr int VEC_IT  = NCOLS / (NT * 4);  // 12 uint4 loads per thread
constexpr int MAX_EQ  = 128;

// dynamic smem layout (uint32 words):
//   keys  [NCOLS]   row as monotone keys
//   hist  [2048]    radix histogram (reused per pass)
//   scanb [32]      warp-total scan buffer
//   sel   [2]       {winning bin, count strictly above}
//   eq    [1+MAX_EQ] {count, indices of keys == threshold}
constexpr int SMEM_WORDS = NCOLS + 2048 + 32 + 2 + 1 + MAX_EQ;
constexpr int SMEM_BYTES = SMEM_WORDS * 4;

__device__ __forceinline__ uint32_t key_of(uint32_t b) {
    // monotone mapping: larger float <=> larger unsigned key
    uint32_t mask = (uint32_t)((int32_t)b >> 31) | 0x80000000u;
    return b ^ mask;
}

__device__ __forceinline__ float relu_of_key(uint32_t k) {
    // positive floats have key MSB set; negatives ReLU to 0
    return (k & 0x80000000u) ? __uint_as_float(k ^ 0x80000000u) : 0.0f;
}

// warp-aggregated histogram increment: one atomic per distinct bin per warp-step
__device__ __forceinline__ void agg_hist_add(uint32_t* hist, uint32_t bin, int lane) {
    unsigned m = __match_any_sync(0xFFFFFFFFu, bin);
    if (lane == (__ffs(m) - 1))
        atomicAdd(&hist[bin], (uint32_t)__popc(m));
}

__global__ __launch_bounds__(NT, 2)
void topk_relu_kernel(const float* __restrict__ x, float* __restrict__ out) {
    extern __shared__ uint32_t smem[];
    uint32_t* keys  = smem;
    uint32_t* hist  = smem + NCOLS;
    uint32_t* scanb = hist + 2048;
    uint32_t* sel   = scanb + 32;
    uint32_t* eq    = sel + 2;        // eq[0]=count, eq[1..]=indices

    const int row  = blockIdx.x;
    const int t    = threadIdx.x;
    const int lane = t & 31;
    const int wid  = t >> 5;
    const uint4* __restrict__ xv = (const uint4*)(x + (size_t)row * NCOLS);
    float* __restrict__ orow = out + (size_t)row * NCOLS;

    // ---- zero pass-0 histogram, init eq counter ----
    for (int i = t; i < 2048; i += NT) hist[i] = 0;
    if (t == 0) eq[0] = 0;
    __syncthreads();

    // ---- load row + build keys + pass-0 (top 11 bits) histogram, fused ----
    #pragma unroll
    for (int it = 0; it < VEC_IT; it++) {
        int vi = it * NT + t;
        uint4 v = xv[vi];
        uint4 kk;
        kk.x = key_of(v.x); kk.y = key_of(v.y);
        kk.z = key_of(v.z); kk.w = key_of(v.w);
        *(uint4*)&keys[vi * 4] = kk;
        agg_hist_add(hist, kk.x >> 21, lane);
        agg_hist_add(hist, kk.y >> 21, lane);
        agg_hist_add(hist, kk.z >> 21, lane);
        agg_hist_add(hist, kk.w >> 21, lane);
    }
    __syncthreads();

    // ---- 3-level MSB-first radix select for the 64th largest key ----
    uint32_t prefix = 0;       // matched high bits so far
    int      prefShift = 32;
    uint32_t R = KSEL;         // remaining rank within matching keys
    uint32_t Tkey = 0;

    #pragma unroll
    for (int pass = 0; pass < 3; pass++) {
        const int shift = (pass == 0) ? 21 : (pass == 1) ? 10 : 0;
        const int nbins = (pass < 2) ? 2048 : 1024;

        if (pass > 0) {
            for (int i = t; i < nbins; i += NT) hist[i] = 0;
            __syncthreads();
            for (int i = t; i < NCOLS; i += NT) {
                uint32_t k = keys[i];
                if ((k >> prefShift) == prefix)
                    atomicAdd(&hist[(k >> shift) & (nbins - 1)], 1u);
            }
            __syncthreads();
        }

        // per-thread partial over G consecutive bins
        const int G = nbins / NT;
        uint32_t p = 0;
        #pragma unroll 4
        for (int j = 0; j < G; j++) p += hist[t * G + j];

        // warp-level inclusive suffix scan of partials
        uint32_t s = p;
        #pragma unroll
        for (int off = 1; off < 32; off <<= 1) {
            uint32_t v = __shfl_down_sync(0xFFFFFFFFu, s, off);
            if (lane + off < 32) s += v;
        }
        if (lane == 0) scanb[wid] = s;   // warp total
        __syncthreads();
        if (t < 32) {
            uint32_t w  = (t < 16) ? scanb[t] : 0u;
            uint32_t ws = w;
            #pragma unroll
            for (int off = 1; off < 32; off <<= 1) {
                uint32_t v = __shfl_down_sync(0xFFFFFFFFu, ws, off);
                if (t + off < 32) ws += v;
            }
            if (t < 16) scanb[t] = ws - w;   // exclusive suffix over warps above
        }
        __syncthreads();

        // count strictly above my first (highest-index) bin
        uint32_t c = (s - p) + scanb[wid];
        for (int j = G - 1; j >= 0; j--) {
            uint32_t h = hist[t * G + j];
            if (c < R && c + h >= R) { sel[0] = (uint32_t)(t * G + j); sel[1] = c; }
            c += h;
        }
        __syncthreads();

        uint32_t d = sel[0];
        R -= sel[1];
        if (pass == 0)      { prefix = d;                  prefShift = 21; }
        else if (pass == 1) { prefix = (prefix << 11) | d; prefShift = 10; }
        else                { Tkey   = (prefix << 10) | d; }
        __syncthreads();   // all threads consumed sel before hist/sel reuse
    }
    const uint32_t keepEq = R;               // how many keys == Tkey to keep
    const float    tval   = relu_of_key(Tkey);

    // ---- output pass: keep k > Tkey; collect exact ties ----
    #pragma unroll
    for (int it = 0; it < VEC_IT; it++) {
        int vi = it * NT + t;
        uint4 kk = *(const uint4*)&keys[vi * 4];
        uint32_t ka[4] = {kk.x, kk.y, kk.z, kk.w};
        float    oa[4];
        #pragma unroll
        for (int j = 0; j < 4; j++) {
            uint32_t k = ka[j];
            float v = 0.0f;
            if (k > Tkey) {
                v = relu_of_key(k);
            } else if (k == Tkey) {
                uint32_t p = atomicAdd(&eq[0], 1u);
                if (p < MAX_EQ) eq[1 + p] = (uint32_t)(vi * 4 + j);
            }
            oa[j] = v;
        }
        float4 o = make_float4(oa[0], oa[1], oa[2], oa[3]);
        *(float4*)&orow[vi * 4] = o;
    }
    __syncthreads();

    // ---- resolve ties: keep the keepEq equal-keys with smallest indices ----
    uint32_t ne = eq[0];
    if (ne > MAX_EQ) ne = MAX_EQ;
    if (ne <= keepEq) {
        for (uint32_t e = t; e < ne; e += NT) orow[eq[1 + e]] = tval;
    } else {
        for (uint32_t e = t; e < ne; e += NT) {
            uint32_t i = eq[1 + e];
            uint32_t cnt = 0;
            for (uint32_t j = 0; j < ne; j++) cnt += (eq[1 + j] < i);
            if (cnt < keepEq) orow[i] = tval;
        }
    }
}

extern "C" void kernel_launch(void* const* d_in, const int* in_sizes, int n_in,
                              void* d_out, int out_size) {
    const float* x = (const float*)d_in[0];
    float* out = (float*)d_out;
    const int rows = in_sizes[0] / NCOLS;

    cudaFuncSetAttribute(topk_relu_kernel,
                         cudaFuncAttributeMaxDynamicSharedMemorySize, SMEM_BYTES);
    topk_relu_kernel<<<rows, NT, SMEM_BYTES>>>(x, out);
}

// round 3
// speedup vs baseline: 1.8036x; 1.8036x over previous
#include <cuda_runtime.h>
#include <cstdint>

// Top-64 per row with ReLU, zeros elsewhere. One CTA per row.
// Pass 0: read row from gmem, per-warp privatized 512-bin histogram on the top
//         9 key bits (match_any leader RMW, no atomics).
// Select: suffix-scan histogram -> bin holding the 64th-largest key.
// Pass 1: re-read row (L2 hit), write output (definitely-above -> ReLU value,
//         below -> 0), collect ~hundreds of candidates from the boundary bin.
// Exact threshold via 8-bit radix select over the candidates; ties broken by
// lowest index (jax.lax.top_k semantics); scatter kept candidates.

constexpr int NCOLS    = 24576;
constexpr int NT       = 512;              // 16 warps
constexpr int NW       = NT / 32;
constexpr int KSEL     = 64;
constexpr int VEC_IT   = NCOLS / (NT * 4); // 12 uint4 per thread
constexpr int HB       = 512;              // first-level bins (top 9 bits)
constexpr int CAND_MAX = 2048;
constexpr int MAX_EQ   = 128;

// smem words
constexpr int W_WHIST = NW * HB;   // 8192
constexpr int W_HIST  = 512;
constexpr int SMEM_WORDS = W_WHIST + W_HIST + 32 + 4 + 2 + CAND_MAX + CAND_MAX + MAX_EQ;
constexpr int SMEM_BYTES = SMEM_WORDS * 4;

__device__ __forceinline__ uint32_t key_of(uint32_t b) {
    uint32_t mask = (uint32_t)((int32_t)b >> 31) | 0x80000000u;
    return b ^ mask;  // larger float <=> larger unsigned key
}
__device__ __forceinline__ float relu_of_key(uint32_t k) {
    return (k & 0x80000000u) ? __uint_as_float(k ^ 0x80000000u) : 0.0f;
}

// suffix-select: given per-thread bin count v for bin t (t<nbins), find the bin
// where the suffix count crosses rank Kre. Writes sel={bin, strictly_above, count}.
__device__ __forceinline__ void suffix_select(
    uint32_t v, uint32_t* scanb, uint32_t* sel,
    int nbins, uint32_t Kre, int t, int lane, int wid)
{
    uint32_t s = v;  // inclusive suffix within warp (higher lane = higher bin)
    #pragma unroll
    for (int off = 1; off < 32; off <<= 1) {
        uint32_t u = __shfl_down_sync(0xFFFFFFFFu, s, off);
        if (lane + off < 32) s += u;
    }
    const int nw = nbins >> 5;
    if (lane == 0 && wid < nw) scanb[wid] = s;
    __syncthreads();
    if (t < 32) {
        uint32_t w = (t < nw) ? scanb[t] : 0u;
        uint32_t ws = w;
        #pragma unroll
        for (int off = 1; off < 32; off <<= 1) {
            uint32_t u = __shfl_down_sync(0xFFFFFFFFu, ws, off);
            if (t + off < 32) ws += u;
        }
        if (t < nw) scanb[t] = ws - w;   // exclusive suffix over warps above
    }
    __syncthreads();
    if (t < nbins) {
        uint32_t above = (s - v) + scanb[wid];
        if (above < Kre && above + v >= Kre) {
            sel[0] = (uint32_t)t; sel[1] = above; sel[2] = v;
        }
    }
    __syncthreads();
}

__global__ __launch_bounds__(NT, 3)
void topk_relu_kernel(const float* __restrict__ x, float* __restrict__ out) {
    extern __shared__ uint32_t smem[];
    uint32_t* whist = smem;                    // [NW][HB]
    uint32_t* hist  = whist + W_WHIST;         // [512]
    uint32_t* scanb = hist + W_HIST;           // [32]
    uint32_t* sel   = scanb + 32;              // [4]
    uint32_t* cnt   = sel + 4;                 // [0]=cands, [1]=eq
    uint32_t* ck    = cnt + 2;                 // [CAND_MAX] candidate keys
    uint32_t* ci    = ck + CAND_MAX;           // [CAND_MAX] candidate indices
    uint32_t* eqi   = ci + CAND_MAX;           // [MAX_EQ]

    const int row  = blockIdx.x;
    const int t    = threadIdx.x;
    const int lane = t & 31;
    const int wid  = t >> 5;
    const uint4* __restrict__ xv = (const uint4*)(x + (size_t)row * NCOLS);
    float* __restrict__ orow = out + (size_t)row * NCOLS;

    uint32_t* wh = whist + wid * HB;

    // ---- init ----
    for (int i = t; i < W_WHIST; i += NT) whist[i] = 0;
    if (t == 0) { cnt[0] = 0; cnt[1] = 0; }
    __syncthreads();

    // ---- pass 0: read row, per-warp 512-bin histogram (no atomics) ----
    #pragma unroll 4
    for (int it = 0; it < VEC_IT; it++) {
        int vi = it * NT + t;
        uint4 v = xv[vi];
        uint32_t ka[4] = { key_of(v.x), key_of(v.y), key_of(v.z), key_of(v.w) };
        #pragma unroll
        for (int j = 0; j < 4; j++) {
            uint32_t bin = ka[j] >> 23;
            unsigned m = __match_any_sync(0xFFFFFFFFu, bin);
            if (lane == (__ffs(m) - 1)) wh[bin] += (uint32_t)__popc(m);
        }
    }
    __syncthreads();

    // ---- reduce per-warp hists; select first-level bin ----
    uint32_t v0 = 0;
    {
        #pragma unroll
        for (int w = 0; w < NW; w++) v0 += whist[w * HB + t];
    }
    suffix_select(v0, scanb, sel, HB, KSEL, t, lane, wid);

    uint32_t P  = sel[0];       // matched prefix (bits >= sh)
    uint32_t R  = KSEL - sel[1];
    uint32_t bc = sel[2];       // boundary-bin count
    int sh = 23;
    __syncthreads();

    // ---- rare: refine prefix until boundary set fits the candidate buffer ----
    while (bc > CAND_MAX && sh > 0) {
        int nsh = (sh >= 8) ? sh - 8 : 0;
        int nb  = 1 << (sh - nsh);
        for (int i = t; i < nb; i += NT) hist[i] = 0;
        __syncthreads();
        for (int i = t; i < NCOLS; i += NT) {
            uint32_t k = key_of(__float_as_uint(__ldcs(((const float*)xv) + i)));
            if ((k >> sh) == P) {
                uint32_t bin = (k >> nsh) & (nb - 1);
                unsigned m = __match_any_sync(__activemask(), bin);
                if ((__activemask() & (1u << (__ffs(m) - 1))) && lane == (__ffs(m) - 1))
                    atomicAdd(&hist[bin], (uint32_t)__popc(m));
            }
        }
        __syncthreads();
        uint32_t hv = (t < nb) ? hist[t] : 0u;
        suffix_select(hv, scanb, sel, nb, R, t, lane, wid);
        P  = (P << (sh - nsh)) | sel[0];
        R -= sel[1];
        bc = sel[2];
        sh = nsh;
        __syncthreads();
    }

    const uint32_t Pq  = P;
    const int      shq = sh;

    // ---- pass 1: re-read (L2), write output, collect boundary candidates ----
    #pragma unroll 4
    for (int it = 0; it < VEC_IT; it++) {
        int vi = it * NT + t;
        uint4 v = __ldcs(&xv[vi]);
        uint32_t ka[4] = { key_of(v.x), key_of(v.y), key_of(v.z), key_of(v.w) };
        float oa[4];
        #pragma unroll
        for (int j = 0; j < 4; j++) {
            uint32_t k  = ka[j];
            uint32_t hi = k >> shq;
            float o = 0.0f;
            if (hi > Pq) {
                o = relu_of_key(k);
            } else if (hi == Pq) {
                uint32_t p = atomicAdd(&cnt[0], 1u);
                if (p < CAND_MAX) { ck[p] = k; ci[p] = (uint32_t)(vi * 4 + j); }
            }
            oa[j] = o;
        }
        float4 o4 = make_float4(oa[0], oa[1], oa[2], oa[3]);
        __stcs((float4*)&orow[vi * 4], o4);
    }
    __syncthreads();

    uint32_t nc = cnt[0];
    if (nc > CAND_MAX) nc = CAND_MAX;

    // ---- exact threshold: 8-bit radix select over candidates ----
    uint32_t Pc = Pq;
    int shc = shq;
    uint32_t Rr = R;
    while (shc > 0) {
        int nsh = (shc >= 8) ? shc - 8 : 0;
        int nb  = 1 << (shc - nsh);
        for (int i = t; i < nb; i += NT) hist[i] = 0;
        __syncthreads();
        for (uint32_t i = t; i < nc; i += NT) {
            uint32_t k = ck[i];
            if ((k >> shc) == Pc)
                atomicAdd(&hist[(k >> nsh) & (nb - 1)], 1u);
        }
        __syncthreads();
        uint32_t hv = (t < nb) ? hist[t] : 0u;
        suffix_select(hv, scanb, sel, nb, Rr, t, lane, wid);
        Pc  = (Pc << (shc - nsh)) | sel[0];
        Rr -= sel[1];
        shc = nsh;
        __syncthreads();
    }
    const uint32_t Tkey   = Pc;
    const uint32_t keepEq = Rr;                 // # threshold-equal keys to keep
    const float    tval   = relu_of_key(Tkey);

    // ---- scatter strictly-above candidates; collect exact ties ----
    for (uint32_t i = t; i < nc; i += NT) {
        uint32_t k = ck[i];
        if (k > Tkey) {
            orow[ci[i]] = relu_of_key(k);
        } else if (k == Tkey) {
            uint32_t p = atomicAdd(&cnt[1], 1u);
            if (p < MAX_EQ) eqi[p] = ci[i];
        }
    }
    __syncthreads();

    // ---- ties: keep the keepEq equal-keys with smallest indices ----
    uint32_t ne = cnt[1];
    if (ne > MAX_EQ) ne = MAX_EQ;
    if (ne <= keepEq) {
        for (uint32_t e = t; e < ne; e += NT) orow[eqi[e]] = tval;
    } else {
        for (uint32_t e = t; e < ne; e += NT) {
            uint32_t idx = eqi[e];
            uint32_t c = 0;
            for (uint32_t j = 0; j < ne; j++) c += (eqi[j] < idx);
            if (c < keepEq) orow[idx] = tval;
        }
    }
}

extern "C" void kernel_launch(void* const* d_in, const int* in_sizes, int n_in,
                              void* d_out, int out_size) {
    const float* x = (const float*)d_in[0];
    float* out = (float*)d_out;
    const int rows = in_sizes[0] / NCOLS;

    cudaFuncSetAttribute(topk_relu_kernel,
                         cudaFuncAttributeMaxDynamicSharedMemorySize, SMEM_BYTES);
    topk_relu_kernel<<<rows, NT, SMEM_BYTES>>>(x, out);
}

// round 5
// speedup vs baseline: 2.2288x; 1.2358x over previous
#include <cuda_runtime.h>
#include <cstdint>

// Top-64 per row with ReLU, zeros elsewhere. One CTA per row.
// Pass 0: read row; per-warp REGISTER histogram over 32 bins (top 5 key bits)
//         via bit-plane ballots — no SMEM, no atomics, ~0.35 instr/value.
// Select: 32-bin suffix scan in one warp -> bin containing the 64th-largest.
// Pass 1: re-read row (L2-resident), write output (definitely-above -> ReLU,
//         below -> 0), collect boundary-bin candidates (~hundreds) via direct
//         key-interval compares (no per-value shift).
// Exact threshold: 8-bit radix select over candidates; ties broken by lowest
// index (jax.lax.top_k semantics). Generic refinement loop for fat bins.

constexpr int NCOLS    = 24576;
constexpr int NT       = 512;              // 16 warps
constexpr int NW       = NT / 32;
constexpr int KSEL     = 64;
constexpr int VEC_IT   = NCOLS / (NT * 4); // 12 uint4 per thread
constexpr int CAND_MAX = 2048;
constexpr int MAX_EQ   = 128;

// smem words
constexpr int W_WHIST = NW * 32;    // 512
constexpr int W_HIST  = 256;        // radix rounds (<=8 bits)
constexpr int SMEM_WORDS = W_WHIST + W_HIST + 32 + 4 + 2 + CAND_MAX + CAND_MAX + MAX_EQ;
constexpr int SMEM_BYTES = SMEM_WORDS * 4;

__device__ __forceinline__ uint32_t key_of(uint32_t b) {
    uint32_t mask = (uint32_t)((int32_t)b >> 31) | 0x80000000u;
    return b ^ mask;  // larger float <=> larger unsigned key
}
__device__ __forceinline__ float relu_of_key(uint32_t k) {
    return (k & 0x80000000u) ? __uint_as_float(k ^ 0x80000000u) : 0.0f;
}

// suffix-select over nbins (<=512): thread t holds count v of bin t. Finds bin
// where suffix count crosses rank Kre. Writes sel={bin, strictly_above, count}.
__device__ __forceinline__ void suffix_select(
    uint32_t v, uint32_t* scanb, uint32_t* sel,
    int nbins, uint32_t Kre, int t, int lane, int wid)
{
    uint32_t s = v;  // inclusive suffix within warp
    #pragma unroll
    for (int off = 1; off < 32; off <<= 1) {
        uint32_t u = __shfl_down_sync(0xFFFFFFFFu, s, off);
        if (lane + off < 32) s += u;
    }
    const int nw = (nbins + 31) >> 5;
    if (lane == 0 && wid < nw) scanb[wid] = s;
    __syncthreads();
    if (t < 32) {
        uint32_t w = (t < nw) ? scanb[t] : 0u;
        uint32_t ws = w;
        #pragma unroll
        for (int off = 1; off < 32; off <<= 1) {
            uint32_t u = __shfl_down_sync(0xFFFFFFFFu, ws, off);
            if (t + off < 32) ws += u;
        }
        if (t < nw) scanb[t] = ws - w;   // exclusive suffix over warps above
    }
    __syncthreads();
    if (t < nbins) {
        uint32_t above = (s - v) + scanb[wid];
        if (above < Kre && above + v >= Kre) {
            sel[0] = (uint32_t)t; sel[1] = above; sel[2] = v;
        }
    }
    __syncthreads();
}

__global__ __launch_bounds__(NT, 4)
void topk_relu_kernel(const float* __restrict__ x, float* __restrict__ out) {
    extern __shared__ uint32_t smem[];
    uint32_t* whist = smem;                    // [NW][32]
    uint32_t* hist  = whist + W_WHIST;         // [256]
    uint32_t* scanb = hist + W_HIST;           // [32]
    uint32_t* sel   = scanb + 32;              // [4]
    uint32_t* cnt   = sel + 4;                 // [0]=cands, [1]=eq
    uint32_t* ck    = cnt + 2;                 // [CAND_MAX] candidate keys
    uint32_t* ci    = ck + CAND_MAX;           // [CAND_MAX] candidate indices
    uint32_t* eqi   = ci + CAND_MAX;           // [MAX_EQ]

    const int row  = blockIdx.x;
    const int t    = threadIdx.x;
    const int lane = t & 31;
    const int wid  = t >> 5;
    const uint4* __restrict__ xv = (const uint4*)(x + (size_t)row * NCOLS);
    float* __restrict__ orow = out + (size_t)row * NCOLS;

    if (t == 0) { cnt[0] = 0; cnt[1] = 0; }
    __syncthreads();

    // ---- pass 0: register histogram over 32 bins via bit-plane ballots ----
    // lane L accumulates the count of values whose top-5 key bits == L.
    const uint32_t sm0 = (lane & 1)  ? 0xFFFFFFFFu : 0u;
    const uint32_t sm1 = (lane & 2)  ? 0xFFFFFFFFu : 0u;
    const uint32_t sm2 = (lane & 4)  ? 0xFFFFFFFFu : 0u;
    const uint32_t sm3 = (lane & 8)  ? 0xFFFFFFFFu : 0u;
    const uint32_t sm4 = (lane & 16) ? 0xFFFFFFFFu : 0u;
    uint32_t mycnt = 0;
    #pragma unroll 4
    for (int it = 0; it < VEC_IT; it++) {
        uint4 v = xv[it * NT + t];
        uint32_t ka[4] = { key_of(v.x), key_of(v.y), key_of(v.z), key_of(v.w) };
        #pragma unroll
        for (int j = 0; j < 4; j++) {
            uint32_t bin = ka[j] >> 27;
            uint32_t b0 = __ballot_sync(0xFFFFFFFFu, bin & 1);
            uint32_t b1 = __ballot_sync(0xFFFFFFFFu, bin & 2);
            uint32_t b2 = __ballot_sync(0xFFFFFFFFu, bin & 4);
            uint32_t b3 = __ballot_sync(0xFFFFFFFFu, bin & 8);
            uint32_t b4 = __ballot_sync(0xFFFFFFFFu, bin & 16);
            uint32_t m = (b0 ^ ~sm0) & (b1 ^ ~sm1) & (b2 ^ ~sm2)
                       & (b3 ^ ~sm3) & (b4 ^ ~sm4);
            mycnt += __popc(m);
        }
    }
    whist[wid * 32 + lane] = mycnt;
    __syncthreads();

    // ---- reduce 16 warps -> 32-bin hist; suffix-select in warp 0 ----
    if (t < 32) {
        uint32_t c = 0;
        #pragma unroll
        for (int w = 0; w < NW; w++) c += whist[w * 32 + t];
        uint32_t s = c;
        #pragma unroll
        for (int off = 1; off < 32; off <<= 1) {
            uint32_t u = __shfl_down_sync(0xFFFFFFFFu, s, off);
            if (t + off < 32) s += u;
        }
        uint32_t above = s - c;
        if (above < KSEL && above + c >= KSEL) {
            sel[0] = (uint32_t)t; sel[1] = above; sel[2] = c;
        }
    }
    __syncthreads();

    uint32_t P  = sel[0];        // matched prefix (key >> sh == P)
    uint32_t R  = KSEL - sel[1]; // rank within boundary bin
    uint32_t bc = sel[2];        // boundary-bin population
    int sh = 27;
    __syncthreads();

    // ---- rare: refine prefix until boundary set fits candidate buffer ----
    while (bc > CAND_MAX && sh > 0) {
        int nsh = (sh >= 8) ? sh - 8 : 0;
        int nb  = 1 << (sh - nsh);
        for (int i = t; i < nb; i += NT) hist[i] = 0;
        __syncthreads();
        for (int i = t; i < NCOLS; i += NT) {
            uint32_t k = key_of(__float_as_uint(((const float*)xv)[i]));
            if ((k >> sh) == P)
                atomicAdd(&hist[(k >> nsh) & (nb - 1)], 1u);
        }
        __syncthreads();
        uint32_t hv = (t < nb) ? hist[t] : 0u;
        suffix_select(hv, scanb, sel, nb, R, t, lane, wid);
        P  = (P << (sh - nsh)) | sel[0];
        R -= sel[1];
        bc = sel[2];
        sh = nsh;
        __syncthreads();
    }

    const uint32_t Pq  = P;
    const int      shq = sh;
    // key-space interval of the boundary bin: [kLo, kHi] inclusive
    const uint32_t kLo = Pq << shq;
    const uint32_t kHi = (uint32_t)((((uint64_t)Pq + 1ull) << shq) - 1ull);

    // ---- pass 1: re-read (L2), write output, collect boundary candidates ----
    #pragma unroll 4
    for (int it = 0; it < VEC_IT; it++) {
        int vi = it * NT + t;
        uint4 v = __ldcs(&xv[vi]);
        uint32_t ka[4] = { key_of(v.x), key_of(v.y), key_of(v.z), key_of(v.w) };
        float oa[4];
        #pragma unroll
        for (int j = 0; j < 4; j++) {
            uint32_t k = ka[j];
            float o = 0.0f;
            if (k > kHi) {
                o = relu_of_key(k);
            } else if (k >= kLo) {
                uint32_t p = atomicAdd(&cnt[0], 1u);
                if (p < CAND_MAX) { ck[p] = k; ci[p] = (uint32_t)(vi * 4 + j); }
            }
            oa[j] = o;
        }
        float4 o4 = make_float4(oa[0], oa[1], oa[2], oa[3]);
        __stcs((float4*)&orow[vi * 4], o4);
    }
    __syncthreads();

    uint32_t nc = cnt[0];
    if (nc > CAND_MAX) nc = CAND_MAX;

    // ---- exact threshold: 8-bit radix select over candidates ----
    uint32_t Pc = Pq;
    int shc = shq;
    uint32_t Rr = R;
    while (shc > 0) {
        int nsh = (shc >= 8) ? shc - 8 : 0;
        int nb  = 1 << (shc - nsh);
        for (int i = t; i < nb; i += NT) hist[i] = 0;
        __syncthreads();
        for (uint32_t i = t; i < nc; i += NT) {
            uint32_t k = ck[i];
            if ((k >> shc) == Pc)
                atomicAdd(&hist[(k >> nsh) & (nb - 1)], 1u);
        }
        __syncthreads();
        uint32_t hv = (t < nb) ? hist[t] : 0u;
        suffix_select(hv, scanb, sel, nb, Rr, t, lane, wid);
        Pc  = (Pc << (shc - nsh)) | sel[0];
        Rr -= sel[1];
        shc = nsh;
        __syncthreads();
    }
    const uint32_t Tkey   = Pc;
    const uint32_t keepEq = Rr;                 // # threshold-equal keys to keep
    const float    tval   = relu_of_key(Tkey);

    // ---- scatter strictly-above candidates; collect exact ties ----
    for (uint32_t i = t; i < nc; i += NT) {
        uint32_t k = ck[i];
        if (k > Tkey) {
            orow[ci[i]] = relu_of_key(k);
        } else if (k == Tkey) {
            uint32_t p = atomicAdd(&cnt[1], 1u);
            if (p < MAX_EQ) eqi[p] = ci[i];
        }
    }
    __syncthreads();

    // ---- ties: keep the keepEq equal-keys with smallest indices ----
    uint32_t ne = cnt[1];
    if (ne > MAX_EQ) ne = MAX_EQ;
    if (ne <= keepEq) {
        for (uint32_t e = t; e < ne; e += NT) orow[eqi[e]] = tval;
    } else {
        for (uint32_t e = t; e < ne; e += NT) {
            uint32_t idx = eqi[e];
            uint32_t c = 0;
            for (uint32_t j = 0; j < ne; j++) c += (eqi[j] < idx);
            if (c < keepEq) orow[idx] = tval;
        }
    }
}

extern "C" void kernel_launch(void* const* d_in, const int* in_sizes, int n_in,
                              void* d_out, int out_size) {
    const float* x = (const float*)d_in[0];
    float* out = (float*)d_out;
    const int rows = in_sizes[0] / NCOLS;

    cudaFuncSetAttribute(topk_relu_kernel,
                         cudaFuncAttributeMaxDynamicSharedMemorySize, SMEM_BYTES);
    topk_relu_kernel<<<rows, NT, SMEM_BYTES>>>(x, out);
}

// round 6
// speedup vs baseline: 3.1158x; 1.3980x over previous
#include <cuda_runtime.h>
#include <cstdint>

// Top-64 per row with ReLU, zeros elsewhere. One CTA per row, SINGLE data pass.
// Main pass: read row once, write zeros to out, append x>2.0 candidates to SMEM
//            (counter = exact count), count positives.
// Fast path (always for N(0,1)): 64 <= ncand <= 2048 -> 8-bit radix select over
//            candidates finds exact 64th-largest; scatter winners (ReLU'd) over
//            the zeroed output. Ties broken by lowest index (jax.lax.top_k).
// Fallbacks: #pos < 64 -> out = relu(x) exactly; otherwise generic key-space
//            radix refine (correct for any distribution).

constexpr int NCOLS    = 24576;
constexpr int NT       = 512;              // 16 warps
constexpr int NW       = NT / 32;
constexpr int KSEL     = 64;
constexpr int VEC_IT   = NCOLS / (NT * 4); // 12 float4 per thread
constexpr int CAND_MAX = 2048;
constexpr int MAX_EQ   = 128;
constexpr float TCAND  = 2.0f;

constexpr int SMEM_WORDS = 256 + 32 + 4 + 4 + NW + CAND_MAX + CAND_MAX + MAX_EQ;
constexpr int SMEM_BYTES = SMEM_WORDS * 4;

__device__ __forceinline__ uint32_t key_of(uint32_t b) {
    uint32_t mask = (uint32_t)((int32_t)b >> 31) | 0x80000000u;
    return b ^ mask;  // larger float <=> larger unsigned key
}
__device__ __forceinline__ float relu_of_key(uint32_t k) {
    return (k & 0x80000000u) ? __uint_as_float(k ^ 0x80000000u) : 0.0f;
}

// suffix-select over nbins (<=256): thread t holds count v of bin t. Finds bin
// where suffix count crosses rank Kre. Writes sel={bin, strictly_above, count}.
__device__ __forceinline__ void suffix_select(
    uint32_t v, uint32_t* scanb, uint32_t* sel,
    int nbins, uint32_t Kre, int t, int lane, int wid)
{
    uint32_t s = v;  // inclusive suffix within warp
    #pragma unroll
    for (int off = 1; off < 32; off <<= 1) {
        uint32_t u = __shfl_down_sync(0xFFFFFFFFu, s, off);
        if (lane + off < 32) s += u;
    }
    const int nw = (nbins + 31) >> 5;
    if (lane == 0 && wid < nw) scanb[wid] = s;
    __syncthreads();
    if (t < 32) {
        uint32_t w = (t < nw) ? scanb[t] : 0u;
        uint32_t ws = w;
        #pragma unroll
        for (int off = 1; off < 32; off <<= 1) {
            uint32_t u = __shfl_down_sync(0xFFFFFFFFu, ws, off);
            if (t + off < 32) ws += u;
        }
        if (t < nw) scanb[t] = ws - w;   // exclusive suffix over warps above
    }
    __syncthreads();
    if (t < nbins) {
        uint32_t above = (s - v) + scanb[wid];
        if (above < Kre && above + v >= Kre) {
            sel[0] = (uint32_t)t; sel[1] = above; sel[2] = v;
        }
    }
    __syncthreads();
}

__global__ __launch_bounds__(NT, 4)
void topk_relu_kernel(const float* __restrict__ x, float* __restrict__ out) {
    extern __shared__ uint32_t smem[];
    uint32_t* hist  = smem;              // [256]
    uint32_t* scanb = hist + 256;        // [32]
    uint32_t* sel   = scanb + 32;        // [4]
    uint32_t* cnt   = sel + 4;           // [0]=cand, [1]=eq, [2]=npos
    uint32_t* wred  = cnt + 4;           // [NW]
    uint32_t* ck    = wred + NW;         // [CAND_MAX] candidate keys
    uint32_t* ci    = ck + CAND_MAX;     // [CAND_MAX] candidate indices
    uint32_t* eqi   = ci + CAND_MAX;     // [MAX_EQ]

    const int row  = blockIdx.x;
    const int t    = threadIdx.x;
    const int lane = t & 31;
    const int wid  = t >> 5;
    const float4* __restrict__ xv =
        reinterpret_cast<const float4*>(x + (size_t)row * NCOLS);
    float* __restrict__ orow = out + (size_t)row * NCOLS;
    float4* __restrict__ ov = reinterpret_cast<float4*>(orow);

    if (t == 0) { cnt[0] = 0; cnt[1] = 0; }
    __syncthreads();

    // ---- single main pass: read, zero output, collect candidates, count + ----
    uint32_t c0 = 0;
    const float4 z4 = make_float4(0.f, 0.f, 0.f, 0.f);
    #pragma unroll 4
    for (int it = 0; it < VEC_IT; it++) {
        int vi = it * NT + t;
        float4 v = __ldcs(xv + vi);
        c0 += (v.x > 0.0f) + (v.y > 0.0f) + (v.z > 0.0f) + (v.w > 0.0f);
        bool b0 = v.x > TCAND, b1 = v.y > TCAND, b2 = v.z > TCAND, b3 = v.w > TCAND;
        __stcs(ov + vi, z4);
        if (b0 | b1 | b2 | b3) {           // ~9% of iterations
            int base = vi * 4;
            if (b0) { uint32_t p = atomicAdd(&cnt[0], 1u);
                      if (p < CAND_MAX) { ck[p] = __float_as_uint(v.x) | 0x80000000u; ci[p] = base; } }
            if (b1) { uint32_t p = atomicAdd(&cnt[0], 1u);
                      if (p < CAND_MAX) { ck[p] = __float_as_uint(v.y) | 0x80000000u; ci[p] = base + 1; } }
            if (b2) { uint32_t p = atomicAdd(&cnt[0], 1u);
                      if (p < CAND_MAX) { ck[p] = __float_as_uint(v.z) | 0x80000000u; ci[p] = base + 2; } }
            if (b3) { uint32_t p = atomicAdd(&cnt[0], 1u);
                      if (p < CAND_MAX) { ck[p] = __float_as_uint(v.w) | 0x80000000u; ci[p] = base + 3; } }
        }
    }
    // reduce positive count
    #pragma unroll
    for (int off = 16; off > 0; off >>= 1)
        c0 += __shfl_down_sync(0xFFFFFFFFu, c0, off);
    if (lane == 0) wred[wid] = c0;
    __syncthreads();
    if (t == 0) {
        uint32_t s = 0;
        #pragma unroll
        for (int w = 0; w < NW; w++) s += wred[w];
        cnt[2] = s;
    }
    __syncthreads();

    const uint32_t ncand = cnt[0];
    const uint32_t npos  = cnt[2];

    uint32_t Pc, Rr, nc;
    int shc;
    if (ncand >= KSEL && ncand <= CAND_MAX) {
        // ---- fast path: candidates complete and contain the top-64 ----
        Pc = 0; shc = 32; Rr = KSEL; nc = ncand;
    } else if (npos < KSEL) {
        // ---- 64th largest <= 0: output is exactly relu(x) ----
        #pragma unroll 4
        for (int it = 0; it < VEC_IT; it++) {
            int vi = it * NT + t;
            float4 v = __ldcs(xv + vi);
            v.x = fmaxf(v.x, 0.0f); v.y = fmaxf(v.y, 0.0f);
            v.z = fmaxf(v.z, 0.0f); v.w = fmaxf(v.w, 0.0f);
            __stcs(ov + vi, v);
        }
        return;
    } else {
        // ---- generic fallback: key-space radix refine (any distribution) ----
        const uint32_t* xb = reinterpret_cast<const uint32_t*>(x) + (size_t)row * NCOLS;
        uint32_t P = 0, R = KSEL, bc = NCOLS;
        int sh = 32;
        while (bc > CAND_MAX && sh > 0) {
            int nsh = (sh >= 8) ? sh - 8 : 0;
            int nb  = 1 << (sh - nsh);
            for (int i = t; i < nb; i += NT) hist[i] = 0;
            __syncthreads();
            for (int i = t; i < NCOLS; i += NT) {
                uint32_t k = key_of(xb[i]);
                if (sh == 32 || (k >> sh) == P)
                    atomicAdd(&hist[(k >> nsh) & (nb - 1)], 1u);
            }
            __syncthreads();
            uint32_t hv = (t < nb) ? hist[t] : 0u;
            suffix_select(hv, scanb, sel, nb, R, t, lane, wid);
            P  = ((sh == 32) ? 0u : (P << (sh - nsh))) | sel[0];
            R -= sel[1];
            bc = sel[2];
            sh = nsh;
            __syncthreads();
        }
        const uint32_t kLo = (sh == 32) ? 0u : (P << sh);
        const uint32_t kHi = (sh == 32) ? 0xFFFFFFFFu
                             : (uint32_t)(((((uint64_t)P) + 1ull) << sh) - 1ull);
        if (t == 0) cnt[0] = 0;
        __syncthreads();
        for (int i = t; i < NCOLS; i += NT) {
            uint32_t k = key_of(xb[i]);
            if (k > kHi) {
                orow[i] = relu_of_key(k);       // definitely top-64
            } else if (k >= kLo) {
                uint32_t p = atomicAdd(&cnt[0], 1u);
                if (p < CAND_MAX) { ck[p] = k; ci[p] = (uint32_t)i; }
            }
        }
        __syncthreads();
        nc = cnt[0]; if (nc > CAND_MAX) nc = CAND_MAX;
        Pc = P; shc = sh; Rr = R;
    }

    // ---- exact threshold: 8-bit radix select over candidates ----
    while (shc > 0) {
        int nsh = (shc >= 8) ? shc - 8 : 0;
        int nb  = 1 << (shc - nsh);
        for (int i = t; i < nb; i += NT) hist[i] = 0;
        __syncthreads();
        for (uint32_t i = t; i < nc; i += NT) {
            uint32_t k = ck[i];
            if (shc == 32 || (k >> shc) == Pc)
                atomicAdd(&hist[(k >> nsh) & (nb - 1)], 1u);
        }
        __syncthreads();
        uint32_t hv = (t < nb) ? hist[t] : 0u;
        suffix_select(hv, scanb, sel, nb, Rr, t, lane, wid);
        Pc  = ((shc == 32) ? 0u : (Pc << (shc - nsh))) | sel[0];
        Rr -= sel[1];
        shc = nsh;
        __syncthreads();
    }
    const uint32_t Tkey   = Pc;
    const uint32_t keepEq = Rr;                 // # threshold-equal keys to keep
    const float    tval   = relu_of_key(Tkey);

    // ---- scatter strictly-above candidates; collect exact ties ----
    for (uint32_t i = t; i < nc; i += NT) {
        uint32_t k = ck[i];
        if (k > Tkey) {
            orow[ci[i]] = relu_of_key(k);
        } else if (k == Tkey) {
            uint32_t p = atomicAdd(&cnt[1], 1u);
            if (p < MAX_EQ) eqi[p] = ci[i];
        }
    }
    __syncthreads();

    // ---- ties: keep the keepEq equal-keys with smallest indices ----
    uint32_t ne = cnt[1];
    if (ne > MAX_EQ) ne = MAX_EQ;
    if (ne <= keepEq) {
        for (uint32_t e = t; e < ne; e += NT) orow[eqi[e]] = tval;
    } else {
        for (uint32_t e = t; e < ne; e += NT) {
            uint32_t idx = eqi[e];
            uint32_t c = 0;
            for (uint32_t j = 0; j < ne; j++) c += (eqi[j] < idx);
            if (c < keepEq) orow[idx] = tval;
        }
    }
}

extern "C" void kernel_launch(void* const* d_in, const int* in_sizes, int n_in,
                              void* d_out, int out_size) {
    const float* x = (const float*)d_in[0];
    float* out = (float*)d_out;
    const int rows = in_sizes[0] / NCOLS;

    cudaFuncSetAttribute(topk_relu_kernel,
                         cudaFuncAttributeMaxDynamicSharedMemorySize, SMEM_BYTES);
    topk_relu_kernel<<<rows, NT, SMEM_BYTES>>>(x, out);
}

// round 7
// speedup vs baseline: 3.1516x; 1.0115x over previous
#include <cuda_runtime.h>
#include <cstdint>

// Top-64 per row with ReLU, zeros elsewhere. One CTA per row, SINGLE data pass.
// Main pass: read row once, write zeros, append x>2.0 candidates to SMEM
//            (counter = exact count). FMNMX-tree detect keeps the loop at
//            ~8 issue slots per float4.
// Fast path (always for N(0,1)): 64 <= ncand <= 2048 -> 8-bit radix select over
//            candidates finds exact 64th-largest; scatter winners (ReLU'd) over
//            the zeroed output. Ties broken by lowest index (jax.lax.top_k).
// Fallbacks (rare, data-independent correctness): count positives on demand;
//            #pos < 64 -> out = relu(x); else generic key-space radix refine.

constexpr int NCOLS    = 24576;
constexpr int NT       = 512;              // 16 warps
constexpr int NW       = NT / 32;
constexpr int KSEL     = 64;
constexpr int VEC_IT   = NCOLS / (NT * 4); // 12 float4 per thread
constexpr int CAND_MAX = 2048;
constexpr int MAX_EQ   = 128;
constexpr float TCAND  = 2.0f;

constexpr int SMEM_WORDS = 256 + 32 + 4 + 4 + NW + CAND_MAX + CAND_MAX + MAX_EQ;
constexpr int SMEM_BYTES = SMEM_WORDS * 4;

__device__ __forceinline__ uint32_t key_of(uint32_t b) {
    uint32_t mask = (uint32_t)((int32_t)b >> 31) | 0x80000000u;
    return b ^ mask;  // larger float <=> larger unsigned key
}
__device__ __forceinline__ float relu_of_key(uint32_t k) {
    return (k & 0x80000000u) ? __uint_as_float(k ^ 0x80000000u) : 0.0f;
}

// suffix-select over nbins (<=256): thread t holds count v of bin t. Finds bin
// where suffix count crosses rank Kre. Writes sel={bin, strictly_above, count}.
__device__ __forceinline__ void suffix_select(
    uint32_t v, uint32_t* scanb, uint32_t* sel,
    int nbins, uint32_t Kre, int t, int lane, int wid)
{
    uint32_t s = v;  // inclusive suffix within warp
    #pragma unroll
    for (int off = 1; off < 32; off <<= 1) {
        uint32_t u = __shfl_down_sync(0xFFFFFFFFu, s, off);
        if (lane + off < 32) s += u;
    }
    const int nw = (nbins + 31) >> 5;
    if (lane == 0 && wid < nw) scanb[wid] = s;
    __syncthreads();
    if (t < 32) {
        uint32_t w = (t < nw) ? scanb[t] : 0u;
        uint32_t ws = w;
        #pragma unroll
        for (int off = 1; off < 32; off <<= 1) {
            uint32_t u = __shfl_down_sync(0xFFFFFFFFu, ws, off);
            if (t + off < 32) ws += u;
        }
        if (t < nw) scanb[t] = ws - w;   // exclusive suffix over warps above
    }
    __syncthreads();
    if (t < nbins) {
        uint32_t above = (s - v) + scanb[wid];
        if (above < Kre && above + v >= Kre) {
            sel[0] = (uint32_t)t; sel[1] = above; sel[2] = v;
        }
    }
    __syncthreads();
}

__global__ __launch_bounds__(NT, 4)
void topk_relu_kernel(const float* __restrict__ x, float* __restrict__ out) {
    extern __shared__ uint32_t smem[];
    uint32_t* hist  = smem;              // [256]
    uint32_t* scanb = hist + 256;        // [32]
    uint32_t* sel   = scanb + 32;        // [4]
    uint32_t* cnt   = sel + 4;           // [0]=cand, [1]=eq, [2]=npos
    uint32_t* wred  = cnt + 4;           // [NW]
    uint32_t* ck    = wred + NW;         // [CAND_MAX] candidate keys
    uint32_t* ci    = ck + CAND_MAX;     // [CAND_MAX] candidate indices
    uint32_t* eqi   = ci + CAND_MAX;     // [MAX_EQ]

    const int row  = blockIdx.x;
    const int t    = threadIdx.x;
    const int lane = t & 31;
    const int wid  = t >> 5;
    const float4* __restrict__ xv =
        reinterpret_cast<const float4*>(x + (size_t)row * NCOLS);
    float* __restrict__ orow = out + (size_t)row * NCOLS;
    float4* __restrict__ ov = reinterpret_cast<float4*>(orow);

    if (t == 0) { cnt[0] = 0; cnt[1] = 0; }
    __syncthreads();

    // ---- single main pass: read, zero output, collect candidates ----
    const float4 z4 = make_float4(0.f, 0.f, 0.f, 0.f);
    #pragma unroll 4
    for (int it = 0; it < VEC_IT; it++) {
        int vi = it * NT + t;
        float4 v = __ldcs(xv + vi);
        __stcs(ov + vi, z4);
        float vmax = fmaxf(fmaxf(v.x, v.y), fmaxf(v.z, v.w));
        if (vmax > TCAND) {                 // ~9% of iterations
            int base = vi * 4;
            if (v.x > TCAND) { uint32_t p = atomicAdd(&cnt[0], 1u);
                if (p < CAND_MAX) { ck[p] = __float_as_uint(v.x) | 0x80000000u; ci[p] = base; } }
            if (v.y > TCAND) { uint32_t p = atomicAdd(&cnt[0], 1u);
                if (p < CAND_MAX) { ck[p] = __float_as_uint(v.y) | 0x80000000u; ci[p] = base + 1; } }
            if (v.z > TCAND) { uint32_t p = atomicAdd(&cnt[0], 1u);
                if (p < CAND_MAX) { ck[p] = __float_as_uint(v.z) | 0x80000000u; ci[p] = base + 2; } }
            if (v.w > TCAND) { uint32_t p = atomicAdd(&cnt[0], 1u);
                if (p < CAND_MAX) { ck[p] = __float_as_uint(v.w) | 0x80000000u; ci[p] = base + 3; } }
        }
    }
    __syncthreads();

    const uint32_t ncand = cnt[0];

    uint32_t Pc, Rr, nc;
    int shc;
    if (ncand >= KSEL && ncand <= CAND_MAX) {
        // ---- fast path: candidate set complete and contains the top-64 ----
        Pc = 0; shc = 32; Rr = KSEL; nc = ncand;
    } else {
        // ---- rare paths: need the positive count (extra L2-resident pass) ----
        uint32_t c0 = 0;
        #pragma unroll 4
        for (int it = 0; it < VEC_IT; it++) {
            float4 v = __ldcs(xv + it * NT + t);
            c0 += (v.x > 0.0f) + (v.y > 0.0f) + (v.z > 0.0f) + (v.w > 0.0f);
        }
        #pragma unroll
        for (int off = 16; off > 0; off >>= 1)
            c0 += __shfl_down_sync(0xFFFFFFFFu, c0, off);
        if (lane == 0) wred[wid] = c0;
        __syncthreads();
        if (t == 0) {
            uint32_t s = 0;
            #pragma unroll
            for (int w = 0; w < NW; w++) s += wred[w];
            cnt[2] = s;
        }
        __syncthreads();
        const uint32_t npos = cnt[2];

        if (npos < KSEL) {
            // 64th largest <= 0: output is exactly relu(x)
            #pragma unroll 4
            for (int it = 0; it < VEC_IT; it++) {
                int vi = it * NT + t;
                float4 v = __ldcs(xv + vi);
                v.x = fmaxf(v.x, 0.0f); v.y = fmaxf(v.y, 0.0f);
                v.z = fmaxf(v.z, 0.0f); v.w = fmaxf(v.w, 0.0f);
                __stcs(ov + vi, v);
            }
            return;
        }

        // generic fallback: key-space radix refine (any distribution)
        const uint32_t* xb = reinterpret_cast<const uint32_t*>(x) + (size_t)row * NCOLS;
        uint32_t P = 0, R = KSEL, bc = NCOLS;
        int sh = 32;
        while (bc > CAND_MAX && sh > 0) {
            int nsh = (sh >= 8) ? sh - 8 : 0;
            int nb  = 1 << (sh - nsh);
            for (int i = t; i < nb; i += NT) hist[i] = 0;
            __syncthreads();
            for (int i = t; i < NCOLS; i += NT) {
                uint32_t k = key_of(xb[i]);
                if (sh == 32 || (k >> sh) == P)
                    atomicAdd(&hist[(k >> nsh) & (nb - 1)], 1u);
            }
            __syncthreads();
            uint32_t hv = (t < nb) ? hist[t] : 0u;
            suffix_select(hv, scanb, sel, nb, R, t, lane, wid);
            P  = ((sh == 32) ? 0u : (P << (sh - nsh))) | sel[0];
            R -= sel[1];
            bc = sel[2];
            sh = nsh;
            __syncthreads();
        }
        const uint32_t kLo = (sh == 32) ? 0u : (P << sh);
        const uint32_t kHi = (sh == 32) ? 0xFFFFFFFFu
                             : (uint32_t)(((((uint64_t)P) + 1ull) << sh) - 1ull);
        if (t == 0) cnt[0] = 0;
        __syncthreads();
        for (int i = t; i < NCOLS; i += NT) {
            uint32_t k = key_of(xb[i]);
            if (k > kHi) {
                orow[i] = relu_of_key(k);       // definitely top-64
            } else if (k >= kLo) {
                uint32_t p = atomicAdd(&cnt[0], 1u);
                if (p < CAND_MAX) { ck[p] = k; ci[p] = (uint32_t)i; }
            }
        }
        __syncthreads();
        nc = cnt[0]; if (nc > CAND_MAX) nc = CAND_MAX;
        Pc = P; shc = sh; Rr = R;
    }

    // ---- exact threshold: 8-bit radix select over candidates ----
    while (shc > 0) {
        int nsh = (shc >= 8) ? shc - 8 : 0;
        int nb  = 1 << (shc - nsh);
        for (int i = t; i < nb; i += NT) hist[i] = 0;
        __syncthreads();
        for (uint32_t i = t; i < nc; i += NT) {
            uint32_t k = ck[i];
            if (shc == 32 || (k >> shc) == Pc)
                atomicAdd(&hist[(k >> nsh) & (nb - 1)], 1u);
        }
        __syncthreads();
        uint32_t hv = (t < nb) ? hist[t] : 0u;
        suffix_select(hv, scanb, sel, nb, Rr, t, lane, wid);
        Pc  = ((shc == 32) ? 0u : (Pc << (shc - nsh))) | sel[0];
        Rr -= sel[1];
        shc = nsh;
        __syncthreads();
    }
    const uint32_t Tkey   = Pc;
    const uint32_t keepEq = Rr;                 // # threshold-equal keys to keep
    const float    tval   = relu_of_key(Tkey);

    // ---- scatter strictly-above candidates; collect exact ties ----
    for (uint32_t i = t; i < nc; i += NT) {
        uint32_t k = ck[i];
        if (k > Tkey) {
            orow[ci[i]] = relu_of_key(k);
        } else if (k == Tkey) {
            uint32_t p = atomicAdd(&cnt[1], 1u);
            if (p < MAX_EQ) eqi[p] = ci[i];
        }
    }
    __syncthreads();

    // ---- ties: keep the keepEq equal-keys with smallest indices ----
    uint32_t ne = cnt[1];
    if (ne > MAX_EQ) ne = MAX_EQ;
    if (ne <= keepEq) {
        for (uint32_t e = t; e < ne; e += NT) orow[eqi[e]] = tval;
    } else {
        for (uint32_t e = t; e < ne; e += NT) {
            uint32_t idx = eqi[e];
            uint32_t c = 0;
            for (uint32_t j = 0; j < ne; j++) c += (eqi[j] < idx);
            if (c < keepEq) orow[idx] = tval;
        }
    }
}

extern "C" void kernel_launch(void* const* d_in, const int* in_sizes, int n_in,
                              void* d_out, int out_size) {
    const float* x = (const float*)d_in[0];
    float* out = (float*)d_out;
    const int rows = in_sizes[0] / NCOLS;

    cudaFuncSetAttribute(topk_relu_kernel,
                         cudaFuncAttributeMaxDynamicSharedMemorySize, SMEM_BYTES);
    topk_relu_kernel<<<rows, NT, SMEM_BYTES>>>(x, out);
}